// round 5
// baseline (speedup 1.0000x reference)
#include <cuda_runtime.h>
#include <cstdint>
#include <cstddef>

#define T_LEN 8192
#define NBLK 32         // blocks per direction in scan (16 hidden units each)
#define VIT_SMEM  (T_LEN*27)

typedef unsigned long long ull;

// ------------------------- device scratch -------------------------
__device__ float d_x0[(size_t)T_LEN * 1728];
__device__ float d_gx0[(size_t)T_LEN * 2048];
__device__ float d_gx1[(size_t)T_LEN * 2048];
__device__ float d_y0[(size_t)T_LEN * 1024];
__device__ float d_y1[(size_t)T_LEN * 1024];
__device__ float d_featbuf[(size_t)T_LEN * 27];
__device__ ull   d_hbuf[(size_t)2 * T_LEN * 512];   // packed (h, tag) per dir/t/unit

__device__ __forceinline__ float sigmf(float x) {
    return 1.0f / (1.0f + expf(-x));
}

// ---- packed f32x2 helpers (sm_103a) ----
__device__ __forceinline__ ull pack2(float lo, float hi) {
    ull d;
    asm("mov.b64 %0, {%1, %2};" : "=l"(d) : "f"(lo), "f"(hi));
    return d;
}
__device__ __forceinline__ void unpack2(ull v, float& lo, float& hi) {
    asm("mov.b64 {%0, %1}, %2;" : "=f"(lo), "=f"(hi) : "l"(v));
}
__device__ __forceinline__ void fma2(ull& d, ull a, ull b) {
    asm("fma.rn.f32x2 %0, %1, %2, %0;" : "+l"(d) : "l"(a), "l"(b));
}
__device__ __forceinline__ ull ldvol64(const ull* p) {
    ull v;
    asm volatile("ld.volatile.global.b64 %0, [%1];" : "=l"(v) : "l"(p));
    return v;
}
__device__ __forceinline__ void stvol64(ull* p, ull v) {
    asm volatile("st.volatile.global.b64 [%0], %1;" :: "l"(p), "l"(v));
}

// ------------------------- conv feature kernel -------------------------
__global__ void __launch_bounds__(256) conv_kernel(
    const float* __restrict__ f,
    const float* __restrict__ w1, const float* __restrict__ b1,
    const float* __restrict__ w3, const float* __restrict__ b3,
    const float* __restrict__ w5, const float* __restrict__ b5,
    float* __restrict__ x0)
{
    __shared__ float fs[448];
    int t = blockIdx.x;
    const float* ft = f + (size_t)t * 448;
    for (int i = threadIdx.x; i < 448; i += 256) fs[i] = ft[i];
    __syncthreads();
    float* xo = x0 + (size_t)t * 1728;
    for (int o = threadIdx.x; o < 1728; o += 256) {
        float acc;
        if (o < 192) {
            int c = o / 12, p = o % 12;
            acc = b1[c];
            #pragma unroll
            for (int kh = 0; kh < 7; kh++)
                #pragma unroll
                for (int kw = 0; kw < 4; kw++)
                    acc += fs[kh * 64 + p * 4 + kw] * w1[c * 28 + kh * 4 + kw];
        } else if (o < 960) {
            int oo = o - 192;
            int c = oo / 48, r = oo % 48, oh = r / 12, p = r % 12;
            acc = b3[c];
            #pragma unroll
            for (int kh = 0; kh < 4; kh++)
                #pragma unroll
                for (int kw = 0; kw < 12; kw++)
                    acc += fs[(oh + kh) * 64 + p * 4 + kw] * w3[c * 48 + kh * 12 + kw];
        } else {
            int oo = o - 960;
            int c = oo / 48, r = oo % 48, oh = r / 12, p = r % 12;
            acc = b5[c];
            #pragma unroll
            for (int kh = 0; kh < 4; kh++)
                #pragma unroll
                for (int kw = 0; kw < 20; kw++)
                    acc += fs[(oh + kh) * 64 + p * 4 + kw] * w5[c * 80 + kh * 20 + kw];
        }
        xo[o] = acc;
    }
}

// ------------------------- GEMM: C[M,N] = A[M,K] * W[N,K]^T + b1 + b2 ----
#define BM 128
#define BN 128
#define BK 16
__global__ void __launch_bounds__(256) gemm_bias_kernel(
    const float* __restrict__ A, const float* __restrict__ W,
    const float* __restrict__ b1, const float* __restrict__ b2,
    float* __restrict__ C, int M, int N, int K)
{
    __shared__ float As[BK][BM];
    __shared__ float Bs[BK][BN];
    int m0 = blockIdx.y * BM;
    int n0 = blockIdx.x * BN;
    int tid = threadIdx.x;
    int ty = tid >> 4;
    int tx = tid & 15;
    ull acc2[8][4];
    #pragma unroll
    for (int i = 0; i < 8; i++)
        #pragma unroll
        for (int j = 0; j < 4; j++) acc2[i][j] = 0ull;

    for (int kt = 0; kt < K; kt += BK) {
        #pragma unroll
        for (int i = 0; i < 2; i++) {
            int q = tid + i * 256;
            int row = q >> 2;
            int kq = (q & 3) * 4;
            float4 v = *(const float4*)&A[(size_t)(m0 + row) * K + kt + kq];
            As[kq + 0][row] = v.x; As[kq + 1][row] = v.y;
            As[kq + 2][row] = v.z; As[kq + 3][row] = v.w;
            float4 u = *(const float4*)&W[(size_t)(n0 + row) * K + kt + kq];
            Bs[kq + 0][row] = u.x; Bs[kq + 1][row] = u.y;
            Bs[kq + 2][row] = u.z; Bs[kq + 3][row] = u.w;
        }
        __syncthreads();
        #pragma unroll
        for (int k = 0; k < BK; k++) {
            float4 a0 = *(const float4*)&As[k][ty * 8];
            float4 a1 = *(const float4*)&As[k][ty * 8 + 4];
            float4 b0 = *(const float4*)&Bs[k][tx * 8];
            float4 b1v = *(const float4*)&Bs[k][tx * 8 + 4];
            float av[8] = {a0.x, a0.y, a0.z, a0.w, a1.x, a1.y, a1.z, a1.w};
            ull bp[4];
            bp[0] = pack2(b0.x, b0.y);  bp[1] = pack2(b0.z, b0.w);
            bp[2] = pack2(b1v.x, b1v.y); bp[3] = pack2(b1v.z, b1v.w);
            #pragma unroll
            for (int i = 0; i < 8; i++) {
                ull ap = pack2(av[i], av[i]);
                #pragma unroll
                for (int j = 0; j < 4; j++)
                    fma2(acc2[i][j], ap, bp[j]);
            }
        }
        __syncthreads();
    }
    float bsum[8];
    #pragma unroll
    for (int j = 0; j < 8; j++) {
        int col = n0 + tx * 8 + j;
        bsum[j] = b1[col] + b2[col];
    }
    #pragma unroll
    for (int i = 0; i < 8; i++) {
        int row = m0 + ty * 8 + i;
        float c[8];
        #pragma unroll
        for (int j = 0; j < 4; j++)
            unpack2(acc2[i][j], c[2 * j], c[2 * j + 1]);
        float4 v0 = {c[0] + bsum[0], c[1] + bsum[1], c[2] + bsum[2], c[3] + bsum[3]};
        float4 v1 = {c[4] + bsum[4], c[5] + bsum[5], c[6] + bsum[6], c[7] + bsum[7]};
        *(float4*)&C[(size_t)row * N + n0 + tx * 8] = v0;
        *(float4*)&C[(size_t)row * N + n0 + tx * 8 + 4] = v1;
    }
}

// ------------------------- hbuf reset (zero all tags) -------------------------
__global__ void reset_kernel(ull* hb) {
    size_t stride = (size_t)gridDim.x * blockDim.x;
    size_t tot = (size_t)2 * T_LEN * 512;
    for (size_t k = (size_t)blockIdx.x * blockDim.x + threadIdx.x; k < tot; k += stride)
        hb[k] = 0ull;
}

// ------------------------- persistent biLSTM scan (barrier-free) ----------
// Grid: 64 blocks (0..31 fwd, 32..63 bwd), 256 threads = 8 warps.
// Warp w of block b owns units {b*16+2w, b*16+2w+1}: all 4 gates (8 rows).
// Weights in packed f32x2 registers. Release = single st.volatile.b64 of
// (h, tag) per unit — no fence, no flags, no __syncthreads in the loop.
// Consumers poll the (h, tag) words directly; tag hit implies h valid.
__global__ void __launch_bounds__(256, 1) lstm_scan_kernel(
    const float* __restrict__ gxf, const float* __restrict__ gxb,
    const float* __restrict__ whhf, const float* __restrict__ whhb,
    ull* __restrict__ hbuf, float* __restrict__ y, int T, int tag_base)
{
    int bx = blockIdx.x;
    int dir = bx >> 5;               // 0 fwd, 1 bwd
    int b = bx & 31;
    const float* gx = dir ? gxb : gxf;
    const float* whh = dir ? whhb : whhf;
    ull* hb = hbuf + (size_t)dir * T * 512;

    int tid = threadIdx.x;
    int lane = tid & 31;
    int w = tid >> 5;
    int u = lane & 1;                // unit selector for gate lanes / gx shfl

    // weights: row j -> gate g = j>>1, local unit lu = 2w + (j&1)
    ull W2[8][8];
    #pragma unroll
    for (int j = 0; j < 8; j++) {
        int g = j >> 1, lu = 2 * w + (j & 1);
        const float* wr = whh + (size_t)(g * 512 + b * 16 + lu) * 512;
        #pragma unroll
        for (int kk = 0; kk < 8; kk++)
            W2[j][kk] = pack2(wr[lane + 64 * kk], wr[lane + 64 * kk + 32]);
    }

    float c_state = 0.0f;            // meaningful on lanes 0,1

    // gx prefetch: lane (2g+uu) holds gate g of unit 2w+uu, lanes 0..7
    float gxv = 0.0f;
    {
        int t0 = dir ? (T - 1) : 0;
        if (lane < 8)
            gxv = __ldcg(&gx[(size_t)t0 * 2048 + (lane >> 1) * 512 + b * 16 + 2 * w + (lane & 1)]);
    }

    for (int s = 0; s < T; s++) {
        int t = dir ? (T - 1 - s) : s;

        // acquire h_{t-1}: poll packed (h, tag) words; hit => value valid
        float hk[16];
        if (s == 0) {
            #pragma unroll
            for (int k = 0; k < 16; k++) hk[k] = 0.0f;
        } else {
            int tprev = dir ? (t + 1) : (t - 1);
            const ull* hp = hb + (size_t)tprev * 512 + lane;
            int want = tag_base + s;
            unsigned ok = 0;
            do {
                #pragma unroll
                for (int k = 0; k < 16; k++) {
                    if (!(ok & (1u << k))) {
                        ull v = ldvol64(hp + 32 * k);
                        if ((int)(v >> 32) == want) {
                            hk[k] = __uint_as_float((unsigned)v);
                            ok |= 1u << k;
                        }
                    }
                }
            } while (!__all_sync(0xffffffffu, ok == 0xFFFFu));
        }

        ull hk2[8];
        #pragma unroll
        for (int kk = 0; kk < 8; kk++)
            hk2[kk] = pack2(hk[2 * kk], hk[2 * kk + 1]);

        // 8 rows: packed FMA + full butterfly (every lane ends with all sums)
        float a[8];
        #pragma unroll
        for (int j = 0; j < 8; j++) {
            ull acc = 0ull;
            #pragma unroll
            for (int kk = 0; kk < 8; kk++)
                fma2(acc, W2[j][kk], hk2[kk]);
            float lo, hi;
            unpack2(acc, lo, hi);
            float av = lo + hi;
            av += __shfl_xor_sync(0xffffffffu, av, 16);
            av += __shfl_xor_sync(0xffffffffu, av, 8);
            av += __shfl_xor_sync(0xffffffffu, av, 4);
            av += __shfl_xor_sync(0xffffffffu, av, 2);
            av += __shfl_xor_sync(0xffffffffu, av, 1);
            a[j] = av;
        }

        // per-lane gx gate values for unit u (uniform shfl, all lanes)
        float gi  = __shfl_sync(0xffffffffu, gxv, 0 + u);
        float gf_ = __shfl_sync(0xffffffffu, gxv, 2 + u);
        float gg  = __shfl_sync(0xffffffffu, gxv, 4 + u);
        float go  = __shfl_sync(0xffffffffu, gxv, 6 + u);

        if (lane < 2) {
            float iv = sigmf(a[u] + gi);
            float fv = sigmf(a[2 + u] + gf_);
            float gv = tanhf(a[4 + u] + gg);
            float ov = sigmf(a[6 + u] + go);
            c_state = fv * c_state + iv * gv;
            float h = ov * tanhf(c_state);
            int unit = b * 16 + 2 * w + u;
            stvol64(hb + (size_t)t * 512 + unit,
                    pack2(h, __int_as_float(tag_base + s + 1)));
            y[(size_t)t * 1024 + (dir << 9) + unit] = h;
        }

        // prefetch gx for next step (a full step of latency to land)
        if (lane < 8 && s + 1 < T) {
            int tn = dir ? (T - 2 - s) : (s + 1);
            gxv = __ldcg(&gx[(size_t)tn * 2048 + (lane >> 1) * 512 + b * 16 + 2 * w + (lane & 1)]);
        }
    }
}

// ------------------------- h2t projection -------------------------
__global__ void __launch_bounds__(864) h2t_kernel(
    const float* __restrict__ y1, const float* __restrict__ w,
    const float* __restrict__ b, float* __restrict__ feats)
{
    int t = blockIdx.x;
    int wid = threadIdx.x >> 5;
    int lane = threadIdx.x & 31;
    const float* yr = y1 + (size_t)t * 1024;
    const float* wr = w + (size_t)wid * 1024;
    float acc = 0.0f;
    #pragma unroll 8
    for (int k = lane; k < 1024; k += 32)
        acc += yr[k] * wr[k];
    acc += __shfl_xor_sync(0xffffffffu, acc, 16);
    acc += __shfl_xor_sync(0xffffffffu, acc, 8);
    acc += __shfl_xor_sync(0xffffffffu, acc, 4);
    acc += __shfl_xor_sync(0xffffffffu, acc, 2);
    acc += __shfl_xor_sync(0xffffffffu, acc, 1);
    if (lane == 0) feats[(size_t)t * 27 + wid] = acc + b[wid];
}

// ------------------------- Viterbi -------------------------
__global__ void viterbi_kernel(
    const float* __restrict__ feats, const float* __restrict__ trans,
    float* __restrict__ out, int T)
{
    extern __shared__ unsigned char bp[];   // T*27
    __shared__ float fv[27];
    __shared__ float fvn[27];
    __shared__ float term[27];
    int tid = threadIdx.x;

    float tr[27];
    if (tid < 27) {
        #pragma unroll
        for (int p = 0; p < 27; p++) tr[p] = trans[tid * 27 + p];
        fv[tid] = (tid == 25) ? 0.0f : -10000.0f;
    }
    __syncwarp();

    float cur[8], nxt[8];
    if (tid < 27) {
        #pragma unroll
        for (int i = 0; i < 8; i++) cur[i] = feats[(size_t)i * 27 + tid];
    }
    for (int tb = 0; tb < T; tb += 8) {
        if (tid < 27) {
            #pragma unroll
            for (int i = 0; i < 8; i++) {
                int tt = tb + 8 + i;
                nxt[i] = (tt < T) ? feats[(size_t)tt * 27 + tid] : 0.0f;
            }
        }
        #pragma unroll
        for (int i = 0; i < 8; i++) {
            int t = tb + i;
            if (tid < 27) {
                float m = -1e30f; int arg = 0;
                #pragma unroll
                for (int p = 0; p < 27; p++) {
                    float s = fv[p] + tr[p];
                    if (s > m) { m = s; arg = p; }
                }
                fvn[tid] = m + cur[i];
                bp[(size_t)t * 27 + tid] = (unsigned char)arg;
            }
            __syncwarp();
            if (tid < 27) fv[tid] = fvn[tid];
            __syncwarp();
        }
        #pragma unroll
        for (int i = 0; i < 8; i++) cur[i] = nxt[i];
    }

    if (tid < 27) term[tid] = fv[tid] + trans[26 * 27 + tid];
    __syncwarp();
    if (tid == 0) {
        float m = -1e30f; int best = 0;
        #pragma unroll
        for (int p = 0; p < 27; p++)
            if (term[p] > m) { m = term[p]; best = p; }
        out[0] = m;
        int tag = best;
        out[T] = (float)tag;
        for (int t = T - 2; t >= 0; t--) {
            tag = bp[(size_t)(t + 1) * 27 + tag];
            out[1 + t] = (float)tag;
        }
    }
}

// ------------------------- launch -------------------------
extern "C" void kernel_launch(void* const* d_in, const int* in_sizes, int n_in,
                              void* d_out, int out_size)
{
    const float* features = (const float*)d_in[0];
    const float* conv1_w = (const float*)d_in[1];
    const float* conv1_b = (const float*)d_in[2];
    const float* conv3_w = (const float*)d_in[3];
    const float* conv3_b = (const float*)d_in[4];
    const float* conv5_w = (const float*)d_in[5];
    const float* conv5_b = (const float*)d_in[6];
    const float* wih0f = (const float*)d_in[7];
    const float* whh0f = (const float*)d_in[8];
    const float* bih0f = (const float*)d_in[9];
    const float* bhh0f = (const float*)d_in[10];
    const float* wih0r = (const float*)d_in[11];
    const float* whh0r = (const float*)d_in[12];
    const float* bih0r = (const float*)d_in[13];
    const float* bhh0r = (const float*)d_in[14];
    const float* wih1f = (const float*)d_in[15];
    const float* whh1f = (const float*)d_in[16];
    const float* bih1f = (const float*)d_in[17];
    const float* bhh1f = (const float*)d_in[18];
    const float* wih1r = (const float*)d_in[19];
    const float* whh1r = (const float*)d_in[20];
    const float* bih1r = (const float*)d_in[21];
    const float* bhh1r = (const float*)d_in[22];
    const float* h2t_w = (const float*)d_in[23];
    const float* h2t_b = (const float*)d_in[24];
    const float* trans = (const float*)d_in[25];
    float* out = (float*)d_out;

    float *x0, *gx0, *gx1, *y0, *y1, *feats;
    ull* hbuf;
    cudaGetSymbolAddress((void**)&x0, d_x0);
    cudaGetSymbolAddress((void**)&gx0, d_gx0);
    cudaGetSymbolAddress((void**)&gx1, d_gx1);
    cudaGetSymbolAddress((void**)&y0, d_y0);
    cudaGetSymbolAddress((void**)&y1, d_y1);
    cudaGetSymbolAddress((void**)&feats, d_featbuf);
    cudaGetSymbolAddress((void**)&hbuf, d_hbuf);

    cudaFuncSetAttribute(viterbi_kernel,
                         cudaFuncAttributeMaxDynamicSharedMemorySize, VIT_SMEM);

    const int T = T_LEN;

    // 0. zero hbuf tags (runs every graph replay)
    reset_kernel<<<1024, 256>>>(hbuf);

    // 1. conv features
    conv_kernel<<<T, 256>>>(features, conv1_w, conv1_b, conv3_w, conv3_b,
                            conv5_w, conv5_b, x0);

    // 2. layer0 input projections
    dim3 g0(2048 / BN, T / BM);
    gemm_bias_kernel<<<g0, 256>>>(x0, wih0f, bih0f, bhh0f, gx0, T, 2048, 1728);
    gemm_bias_kernel<<<g0, 256>>>(x0, wih0r, bih0r, bhh0r, gx1, T, 2048, 1728);

    // 3. layer0 scan (tags 1..T)
    lstm_scan_kernel<<<2 * NBLK, 256>>>(gx0, gx1, whh0f, whh0r, hbuf, y0, T, 0);

    // 4. layer1 input projections
    gemm_bias_kernel<<<g0, 256>>>(y0, wih1f, bih1f, bhh1f, gx0, T, 2048, 1024);
    gemm_bias_kernel<<<g0, 256>>>(y0, wih1r, bih1r, bhh1r, gx1, T, 2048, 1024);

    // 5. layer1 scan (tags T+1..2T)
    lstm_scan_kernel<<<2 * NBLK, 256>>>(gx0, gx1, whh1f, whh1r, hbuf, y1, T, T);

    // 6. tag projection
    h2t_kernel<<<T, 864>>>(y1, h2t_w, h2t_b, feats);

    // 7. viterbi decode
    viterbi_kernel<<<1, 32, VIT_SMEM>>>(feats, trans, out, T);
}

// round 8
// speedup vs baseline: 2.4658x; 2.4658x over previous
#include <cuda_runtime.h>
#include <cstdint>
#include <cstddef>

#define T_LEN 8192
#define NBLK 32         // blocks per direction in scan (16 hidden units each)
#define VIT_SMEM  (T_LEN*27)

typedef unsigned long long ull;

// ------------------------- device scratch -------------------------
__device__ float d_x0[(size_t)T_LEN * 1728];
__device__ float d_gx0[(size_t)T_LEN * 2048];
__device__ float d_gx1[(size_t)T_LEN * 2048];
__device__ float d_y0[(size_t)T_LEN * 1024];
__device__ float d_y1[(size_t)T_LEN * 1024];
__device__ float d_featbuf[(size_t)T_LEN * 27];
__device__ __align__(128) int d_cnt[128];   // [0]=L0 fwd, [32]=L0 bwd, [64]=L1 fwd, [96]=L1 bwd

__device__ __forceinline__ float sigmf(float x) {
    return 1.0f / (1.0f + expf(-x));
}

// ---- packed f32x2 helpers (sm_103a) ----
__device__ __forceinline__ ull pack2(float lo, float hi) {
    ull d;
    asm("mov.b64 %0, {%1, %2};" : "=l"(d) : "f"(lo), "f"(hi));
    return d;
}
__device__ __forceinline__ void unpack2(ull v, float& lo, float& hi) {
    asm("mov.b64 {%0, %1}, %2;" : "=f"(lo), "=f"(hi) : "l"(v));
}
__device__ __forceinline__ void fma2(ull& d, ull a, ull b) {
    asm("fma.rn.f32x2 %0, %1, %2, %0;" : "+l"(d) : "l"(a), "l"(b));
}
__device__ __forceinline__ int ld_acquire(const int* p) {
    int v;
    asm volatile("ld.acquire.gpu.global.u32 %0, [%1];" : "=r"(v) : "l"(p) : "memory");
    return v;
}
__device__ __forceinline__ void red_release_add(int* p, int v) {
    asm volatile("red.release.gpu.global.add.u32 [%0], %1;" :: "l"(p), "r"(v) : "memory");
}

// ------------------------- conv feature kernel -------------------------
__global__ void __launch_bounds__(256) conv_kernel(
    const float* __restrict__ f,
    const float* __restrict__ w1, const float* __restrict__ b1,
    const float* __restrict__ w3, const float* __restrict__ b3,
    const float* __restrict__ w5, const float* __restrict__ b5,
    float* __restrict__ x0)
{
    __shared__ float fs[448];
    int t = blockIdx.x;
    const float* ft = f + (size_t)t * 448;
    for (int i = threadIdx.x; i < 448; i += 256) fs[i] = ft[i];
    __syncthreads();
    float* xo = x0 + (size_t)t * 1728;
    for (int o = threadIdx.x; o < 1728; o += 256) {
        float acc;
        if (o < 192) {
            int c = o / 12, p = o % 12;
            acc = b1[c];
            #pragma unroll
            for (int kh = 0; kh < 7; kh++)
                #pragma unroll
                for (int kw = 0; kw < 4; kw++)
                    acc += fs[kh * 64 + p * 4 + kw] * w1[c * 28 + kh * 4 + kw];
        } else if (o < 960) {
            int oo = o - 192;
            int c = oo / 48, r = oo % 48, oh = r / 12, p = r % 12;
            acc = b3[c];
            #pragma unroll
            for (int kh = 0; kh < 4; kh++)
                #pragma unroll
                for (int kw = 0; kw < 12; kw++)
                    acc += fs[(oh + kh) * 64 + p * 4 + kw] * w3[c * 48 + kh * 12 + kw];
        } else {
            int oo = o - 960;
            int c = oo / 48, r = oo % 48, oh = r / 12, p = r % 12;
            acc = b5[c];
            #pragma unroll
            for (int kh = 0; kh < 4; kh++)
                #pragma unroll
                for (int kw = 0; kw < 20; kw++)
                    acc += fs[(oh + kh) * 64 + p * 4 + kw] * w5[c * 80 + kh * 20 + kw];
        }
        xo[o] = acc;
    }
}

// ------------------------- GEMM: C[M,N] = A[M,K] * W[N,K]^T + b1 + b2 ----
#define BM 128
#define BN 128
#define BK 16
__global__ void __launch_bounds__(256) gemm_bias_kernel(
    const float* __restrict__ A, const float* __restrict__ W,
    const float* __restrict__ b1, const float* __restrict__ b2,
    float* __restrict__ C, int M, int N, int K)
{
    __shared__ float As[BK][BM];
    __shared__ float Bs[BK][BN];
    int m0 = blockIdx.y * BM;
    int n0 = blockIdx.x * BN;
    int tid = threadIdx.x;
    int ty = tid >> 4;
    int tx = tid & 15;
    ull acc2[8][4];
    #pragma unroll
    for (int i = 0; i < 8; i++)
        #pragma unroll
        for (int j = 0; j < 4; j++) acc2[i][j] = 0ull;

    for (int kt = 0; kt < K; kt += BK) {
        #pragma unroll
        for (int i = 0; i < 2; i++) {
            int q = tid + i * 256;
            int row = q >> 2;
            int kq = (q & 3) * 4;
            float4 v = *(const float4*)&A[(size_t)(m0 + row) * K + kt + kq];
            As[kq + 0][row] = v.x; As[kq + 1][row] = v.y;
            As[kq + 2][row] = v.z; As[kq + 3][row] = v.w;
            float4 u = *(const float4*)&W[(size_t)(n0 + row) * K + kt + kq];
            Bs[kq + 0][row] = u.x; Bs[kq + 1][row] = u.y;
            Bs[kq + 2][row] = u.z; Bs[kq + 3][row] = u.w;
        }
        __syncthreads();
        #pragma unroll
        for (int k = 0; k < BK; k++) {
            float4 a0 = *(const float4*)&As[k][ty * 8];
            float4 a1 = *(const float4*)&As[k][ty * 8 + 4];
            float4 b0 = *(const float4*)&Bs[k][tx * 8];
            float4 b1v = *(const float4*)&Bs[k][tx * 8 + 4];
            float av[8] = {a0.x, a0.y, a0.z, a0.w, a1.x, a1.y, a1.z, a1.w};
            ull bp[4];
            bp[0] = pack2(b0.x, b0.y);  bp[1] = pack2(b0.z, b0.w);
            bp[2] = pack2(b1v.x, b1v.y); bp[3] = pack2(b1v.z, b1v.w);
            #pragma unroll
            for (int i = 0; i < 8; i++) {
                ull ap = pack2(av[i], av[i]);
                #pragma unroll
                for (int j = 0; j < 4; j++)
                    fma2(acc2[i][j], ap, bp[j]);
            }
        }
        __syncthreads();
    }
    float bsum[8];
    #pragma unroll
    for (int j = 0; j < 8; j++) {
        int col = n0 + tx * 8 + j;
        bsum[j] = b1[col] + b2[col];
    }
    #pragma unroll
    for (int i = 0; i < 8; i++) {
        int row = m0 + ty * 8 + i;
        float c[8];
        #pragma unroll
        for (int j = 0; j < 4; j++)
            unpack2(acc2[i][j], c[2 * j], c[2 * j + 1]);
        float4 v0 = {c[0] + bsum[0], c[1] + bsum[1], c[2] + bsum[2], c[3] + bsum[3]};
        float4 v1 = {c[4] + bsum[4], c[5] + bsum[5], c[6] + bsum[6], c[7] + bsum[7]};
        *(float4*)&C[(size_t)row * N + n0 + tx * 8] = v0;
        *(float4*)&C[(size_t)row * N + n0 + tx * 8 + 4] = v1;
    }
}

// ------------------------- counter reset -------------------------
__global__ void reset_kernel() {
    if (threadIdx.x < 128) d_cnt[threadIdx.x] = 0;
}

// ------------------------- dummy (ncu aim: makes launch idx 5 = scan) ----
__global__ void dummy_kernel() {}

// ------------------------- persistent biLSTM scan -------------------------
// Grid: 64 blocks (0..31 fwd, 32..63 bwd), 256 threads = 8 warps.
// Warp w of block b owns units {b*16+2w, b*16+2w+1}: all 4 gates (8 rows),
// weights in packed f32x2 registers.
// Sync per direction: ONE counter word. Producer: block barrier then a single
// red.release.gpu.add from tid 0. Consumer: one lane polls ld.acquire.gpu,
// block barrier wakes the rest, h read once via __ldcg.
__global__ void __launch_bounds__(256, 1) lstm_scan_kernel(
    const float* __restrict__ gxf, const float* __restrict__ gxb,
    const float* __restrict__ whhf, const float* __restrict__ whhb,
    float* __restrict__ y, int* __restrict__ cnt, int T)
{
    int bx = blockIdx.x;
    int dir = bx >> 5;               // 0 fwd, 1 bwd
    int b = bx & 31;
    const float* gx = dir ? gxb : gxf;
    const float* whh = dir ? whhb : whhf;
    int* cn = cnt + dir * 32;        // own 128B line per direction

    int tid = threadIdx.x;
    int lane = tid & 31;
    int w = tid >> 5;
    int u = lane & 1;

    // weights: row j -> gate g = j>>1, local unit lu = 2w + (j&1)
    ull W2[8][8];
    #pragma unroll
    for (int j = 0; j < 8; j++) {
        int g = j >> 1, lu = 2 * w + (j & 1);
        const float* wr = whh + (size_t)(g * 512 + b * 16 + lu) * 512;
        #pragma unroll
        for (int kk = 0; kk < 8; kk++)
            W2[j][kk] = pack2(wr[lane + 64 * kk], wr[lane + 64 * kk + 32]);
    }

    float c_state = 0.0f;            // meaningful on lanes 0,1
    float* ybase = y + (dir << 9);   // column offset dir*512

    // gx prefetch: lane (2g+uu) holds gate g of unit 2w+uu (lanes 0..7)
    float gxv = 0.0f;
    {
        int t0 = dir ? (T - 1) : 0;
        if (lane < 8)
            gxv = __ldcg(&gx[(size_t)t0 * 2048 + (lane >> 1) * 512 + b * 16 + 2 * w + (lane & 1)]);
    }

    for (int s = 0; s < T; s++) {
        int t = dir ? (T - 1 - s) : s;

        float hk[16];
        if (s == 0) {
            #pragma unroll
            for (int k = 0; k < 16; k++) hk[k] = 0.0f;
        } else {
            if (tid == 0) {
                int target = s << 5;          // 32 * s
                while (ld_acquire(cn) < target) { }
            }
            __syncthreads();
            int tprev = dir ? (t + 1) : (t - 1);
            const float* hp = ybase + (size_t)tprev * 1024;
            #pragma unroll
            for (int k = 0; k < 16; k++)
                hk[k] = __ldcg(&hp[lane + 32 * k]);
        }

        ull hk2[8];
        #pragma unroll
        for (int kk = 0; kk < 8; kk++)
            hk2[kk] = pack2(hk[2 * kk], hk[2 * kk + 1]);

        // 8 rows: packed FMA + full butterfly (every lane gets all 8 sums)
        float a[8];
        #pragma unroll
        for (int j = 0; j < 8; j++) {
            ull acc = 0ull;
            #pragma unroll
            for (int kk = 0; kk < 8; kk++)
                fma2(acc, W2[j][kk], hk2[kk]);
            float lo, hi;
            unpack2(acc, lo, hi);
            float av = lo + hi;
            av += __shfl_xor_sync(0xffffffffu, av, 16);
            av += __shfl_xor_sync(0xffffffffu, av, 8);
            av += __shfl_xor_sync(0xffffffffu, av, 4);
            av += __shfl_xor_sync(0xffffffffu, av, 2);
            av += __shfl_xor_sync(0xffffffffu, av, 1);
            a[j] = av;
        }

        // gx gate values for this lane's unit u
        float gi  = __shfl_sync(0xffffffffu, gxv, 0 + u);
        float gf_ = __shfl_sync(0xffffffffu, gxv, 2 + u);
        float gg  = __shfl_sync(0xffffffffu, gxv, 4 + u);
        float go  = __shfl_sync(0xffffffffu, gxv, 6 + u);

        if (lane < 2) {
            float iv = sigmf(a[u] + gi);
            float fv = sigmf(a[2 + u] + gf_);
            float gv = tanhf(a[4 + u] + gg);
            float ov = sigmf(a[6 + u] + go);
            c_state = fv * c_state + iv * gv;
            float h = ov * tanhf(c_state);
            int unit = b * 16 + 2 * w + u;
            __stcg(&ybase[(size_t)t * 1024 + unit], h);
        }

        __syncthreads();                     // all warps' h stores issued
        if (tid == 0) red_release_add(cn, 1);

        // prefetch gx for next step (a full step of latency to land)
        if (lane < 8 && s + 1 < T) {
            int tn = dir ? (T - 2 - s) : (s + 1);
            gxv = __ldcg(&gx[(size_t)tn * 2048 + (lane >> 1) * 512 + b * 16 + 2 * w + (lane & 1)]);
        }
    }
}

// ------------------------- h2t projection -------------------------
__global__ void __launch_bounds__(864) h2t_kernel(
    const float* __restrict__ y1, const float* __restrict__ w,
    const float* __restrict__ b, float* __restrict__ feats)
{
    int t = blockIdx.x;
    int wid = threadIdx.x >> 5;
    int lane = threadIdx.x & 31;
    const float* yr = y1 + (size_t)t * 1024;
    const float* wr = w + (size_t)wid * 1024;
    float acc = 0.0f;
    #pragma unroll 8
    for (int k = lane; k < 1024; k += 32)
        acc += yr[k] * wr[k];
    acc += __shfl_xor_sync(0xffffffffu, acc, 16);
    acc += __shfl_xor_sync(0xffffffffu, acc, 8);
    acc += __shfl_xor_sync(0xffffffffu, acc, 4);
    acc += __shfl_xor_sync(0xffffffffu, acc, 2);
    acc += __shfl_xor_sync(0xffffffffu, acc, 1);
    if (lane == 0) feats[(size_t)t * 27 + wid] = acc + b[wid];
}

// ------------------------- Viterbi -------------------------
__global__ void viterbi_kernel(
    const float* __restrict__ feats, const float* __restrict__ trans,
    float* __restrict__ out, int T)
{
    extern __shared__ unsigned char bp[];   // T*27
    __shared__ float fv[27];
    __shared__ float fvn[27];
    __shared__ float term[27];
    int tid = threadIdx.x;

    float tr[27];
    if (tid < 27) {
        #pragma unroll
        for (int p = 0; p < 27; p++) tr[p] = trans[tid * 27 + p];
        fv[tid] = (tid == 25) ? 0.0f : -10000.0f;
    }
    __syncwarp();

    float cur[8], nxt[8];
    if (tid < 27) {
        #pragma unroll
        for (int i = 0; i < 8; i++) cur[i] = feats[(size_t)i * 27 + tid];
    }
    for (int tb = 0; tb < T; tb += 8) {
        if (tid < 27) {
            #pragma unroll
            for (int i = 0; i < 8; i++) {
                int tt = tb + 8 + i;
                nxt[i] = (tt < T) ? feats[(size_t)tt * 27 + tid] : 0.0f;
            }
        }
        #pragma unroll
        for (int i = 0; i < 8; i++) {
            int t = tb + i;
            if (tid < 27) {
                float m = -1e30f; int arg = 0;
                #pragma unroll
                for (int p = 0; p < 27; p++) {
                    float s = fv[p] + tr[p];
                    if (s > m) { m = s; arg = p; }
                }
                fvn[tid] = m + cur[i];
                bp[(size_t)t * 27 + tid] = (unsigned char)arg;
            }
            __syncwarp();
            if (tid < 27) fv[tid] = fvn[tid];
            __syncwarp();
        }
        #pragma unroll
        for (int i = 0; i < 8; i++) cur[i] = nxt[i];
    }

    if (tid < 27) term[tid] = fv[tid] + trans[26 * 27 + tid];
    __syncwarp();
    if (tid == 0) {
        float m = -1e30f; int best = 0;
        #pragma unroll
        for (int p = 0; p < 27; p++)
            if (term[p] > m) { m = term[p]; best = p; }
        out[0] = m;
        int tag = best;
        out[T] = (float)tag;
        for (int t = T - 2; t >= 0; t--) {
            tag = bp[(size_t)(t + 1) * 27 + tag];
            out[1 + t] = (float)tag;
        }
    }
}

// ------------------------- launch -------------------------
extern "C" void kernel_launch(void* const* d_in, const int* in_sizes, int n_in,
                              void* d_out, int out_size)
{
    const float* features = (const float*)d_in[0];
    const float* conv1_w = (const float*)d_in[1];
    const float* conv1_b = (const float*)d_in[2];
    const float* conv3_w = (const float*)d_in[3];
    const float* conv3_b = (const float*)d_in[4];
    const float* conv5_w = (const float*)d_in[5];
    const float* conv5_b = (const float*)d_in[6];
    const float* wih0f = (const float*)d_in[7];
    const float* whh0f = (const float*)d_in[8];
    const float* bih0f = (const float*)d_in[9];
    const float* bhh0f = (const float*)d_in[10];
    const float* wih0r = (const float*)d_in[11];
    const float* whh0r = (const float*)d_in[12];
    const float* bih0r = (const float*)d_in[13];
    const float* bhh0r = (const float*)d_in[14];
    const float* wih1f = (const float*)d_in[15];
    const float* whh1f = (const float*)d_in[16];
    const float* bih1f = (const float*)d_in[17];
    const float* bhh1f = (const float*)d_in[18];
    const float* wih1r = (const float*)d_in[19];
    const float* whh1r = (const float*)d_in[20];
    const float* bih1r = (const float*)d_in[21];
    const float* bhh1r = (const float*)d_in[22];
    const float* h2t_w = (const float*)d_in[23];
    const float* h2t_b = (const float*)d_in[24];
    const float* trans = (const float*)d_in[25];
    float* out = (float*)d_out;

    float *x0, *gx0, *gx1, *y0, *y1, *feats;
    int* cnt;
    cudaGetSymbolAddress((void**)&x0, d_x0);
    cudaGetSymbolAddress((void**)&gx0, d_gx0);
    cudaGetSymbolAddress((void**)&gx1, d_gx1);
    cudaGetSymbolAddress((void**)&y0, d_y0);
    cudaGetSymbolAddress((void**)&y1, d_y1);
    cudaGetSymbolAddress((void**)&feats, d_featbuf);
    cudaGetSymbolAddress((void**)&cnt, d_cnt);

    cudaFuncSetAttribute(viterbi_kernel,
                         cudaFuncAttributeMaxDynamicSharedMemorySize, VIT_SMEM);

    const int T = T_LEN;

    // launch index:                                            0
    reset_kernel<<<1, 128>>>();

    // 1. conv features                                         1
    conv_kernel<<<T, 256>>>(features, conv1_w, conv1_b, conv3_w, conv3_b,
                            conv5_w, conv5_b, x0);

    // 2. layer0 input projections                              2,3
    dim3 g0(2048 / BN, T / BM);
    gemm_bias_kernel<<<g0, 256>>>(x0, wih0f, bih0f, bhh0f, gx0, T, 2048, 1728);
    gemm_bias_kernel<<<g0, 256>>>(x0, wih0r, bih0r, bhh0r, gx1, T, 2048, 1728);

    // ncu aim: launch idx 4, so idx 5 (ncu -s 5 -c 1) = scan   4
    dummy_kernel<<<1, 32>>>();

    // 3. layer0 scan                                           5  <- profiled
    lstm_scan_kernel<<<2 * NBLK, 256>>>(gx0, gx1, whh0f, whh0r, y0, cnt, T);

    // 4. layer1 input projections                              6,7
    gemm_bias_kernel<<<g0, 256>>>(y0, wih1f, bih1f, bhh1f, gx0, T, 2048, 1024);
    gemm_bias_kernel<<<g0, 256>>>(y0, wih1r, bih1r, bhh1r, gx1, T, 2048, 1024);

    // 5. layer1 scan                                           8
    lstm_scan_kernel<<<2 * NBLK, 256>>>(gx0, gx1, whh1f, whh1r, y1, cnt + 64, T);

    // 6. tag projection                                        9
    h2t_kernel<<<T, 864>>>(y1, h2t_w, h2t_b, feats);

    // 7. viterbi decode                                        10
    viterbi_kernel<<<1, 32, VIT_SMEM>>>(feats, trans, out, T);
}